// round 3
// baseline (speedup 1.0000x reference)
#include <cuda_runtime.h>

typedef unsigned long long ULL;

// ---------------- packed f32x2 helpers (sm_103a FFMA2 path) ----------------
__device__ __forceinline__ ULL pk2(float lo, float hi) {
    ULL r; asm("mov.b64 %0, {%1,%2};" : "=l"(r) : "f"(lo), "f"(hi)); return r;
}
__device__ __forceinline__ void upk2(ULL v, float& lo, float& hi) {
    asm("mov.b64 {%0,%1}, %2;" : "=f"(lo), "=f"(hi) : "l"(v));
}
__device__ __forceinline__ ULL fma2(ULL a, ULL b, ULL c) {
    ULL d; asm("fma.rn.f32x2 %0, %1, %2, %3;" : "=l"(d) : "l"(a), "l"(b), "l"(c)); return d;
}
__device__ __forceinline__ ULL add2(ULL a, ULL b) {
    ULL d; asm("add.rn.f32x2 %0, %1, %2;" : "=l"(d) : "l"(a), "l"(b)); return d;
}

// ---------------- problem constants ----------------
constexpr int K   = 32;      // experts
constexpr int NKP = K / 2;   // expert pairs = 16
constexpr int DI  = 10;      // input size
constexpr int DH  = 20;      // hidden size
constexpr int NHP = DH / 2;  // hidden pairs = 10
constexpr int B   = 262144;
constexpr int THREADS = 128;
constexpr int R   = 2;       // batch rows per thread
constexpr int GRID = B / (R * THREADS);   // 1024

// shared layout in ULL (8B) units
constexpr int U_W1 = 0;                     // [k][hp][i] (h,h+1) pairs : 3200 ULL
constexpr int U_BW = U_W1 + K * NHP * DI;   // [k][hp]{(b1,b1+1),(w2,w2+1)} : 640 ULL
constexpr int U_P  = U_BW + K * NHP * 2;    // [kp][i] (-p[2kp],-p[2kp+1]) : 160 ULL
constexpr int U_END = U_P + NKP * DI;       // 4000 ULL
constexpr int F_B2 = U_END * 2;             // float idx 8000
constexpr int SM_FLOATS = F_B2 + K;         // 8032 floats = 32128 B

__global__ void __launch_bounds__(THREADS)
piecewise_mlp_kernel(const float* __restrict__ in,
                     const float* __restrict__ W1,
                     const float* __restrict__ b1,
                     const float* __restrict__ W2,
                     const float* __restrict__ b2,
                     const float* __restrict__ proto,
                     float* __restrict__ out)
{
    extern __shared__ float sm[];
    ULL* smU = (ULL*)sm;

    // ---- stage weights ----
    for (int idx = threadIdx.x; idx < K * NHP * DI; idx += THREADS) {
        int k = idx / (NHP * DI), rem = idx % (NHP * DI);
        int hp = rem / DI, i = rem % DI;
        smU[U_W1 + idx] = pk2(W1[(k * DH + 2 * hp) * DI + i],
                              W1[(k * DH + 2 * hp + 1) * DI + i]);
    }
    for (int idx = threadIdx.x; idx < K * NHP * 2; idx += THREADS) {
        int k = idx / (NHP * 2), rem = idx % (NHP * 2);
        int hp = rem / 2, w = rem % 2;
        const float* src = (w == 0) ? b1 : W2;   // W2 is [K,1,DH] flat
        smU[U_BW + idx] = pk2(src[k * DH + 2 * hp], src[k * DH + 2 * hp + 1]);
    }
    for (int idx = threadIdx.x; idx < NKP * DI; idx += THREADS) {
        int kp = idx / DI, i = idx % DI;
        smU[U_P + idx] = pk2(-proto[(2 * kp) * DI + i],
                             -proto[(2 * kp + 1) * DI + i]);
    }
    for (int idx = threadIdx.x; idx < K; idx += THREADS)
        sm[F_B2 + idx] = b2[idx];
    __syncthreads();

    // ---- load R=2 batch rows (80B contiguous), build dup packs (x,x) ----
    const int gt = blockIdx.x * THREADS + threadIdx.x;
    const float4* q = (const float4*)(in + (size_t)gt * R * DI);
    ULL x2[R][DI];
    #pragma unroll
    for (int v = 0; v < R * DI / 4; v++) {     // 5 float4 loads
        float4 f = q[v];
        int b0 = v * 4;
        x2[(b0 + 0) / DI][(b0 + 0) % DI] = pk2(f.x, f.x);
        x2[(b0 + 1) / DI][(b0 + 1) % DI] = pk2(f.y, f.y);
        x2[(b0 + 2) / DI][(b0 + 2) % DI] = pk2(f.z, f.z);
        x2[(b0 + 3) / DI][(b0 + 3) % DI] = pk2(f.w, f.w);
    }

    ULL num2[R], den2[R];
    #pragma unroll
    for (int r = 0; r < R; r++) { num2[r] = 0ull; den2[r] = 0ull; }

    const ULL* w1p = smU + U_W1;
    const ULL* bwp = smU + U_BW;
    const ULL* ppp = smU + U_P;

    #pragma unroll 1
    for (int kp = 0; kp < NKP; kp++) {
        // ---- gating for expert pair (2kp, 2kp+1), both rows ----
        const ulonglong2* pq = (const ulonglong2*)(ppp + kp * DI);
        ulonglong2 p0 = pq[0], p1 = pq[1], p2 = pq[2], p3 = pq[3], p4 = pq[4];
        ULL e2[R];
        #pragma unroll
        for (int r = 0; r < R; r++) {
            ULL d2 = 0ull, df;
            df = add2(x2[r][0], p0.x); d2 = fma2(df, df, d2);
            df = add2(x2[r][1], p0.y); d2 = fma2(df, df, d2);
            df = add2(x2[r][2], p1.x); d2 = fma2(df, df, d2);
            df = add2(x2[r][3], p1.y); d2 = fma2(df, df, d2);
            df = add2(x2[r][4], p2.x); d2 = fma2(df, df, d2);
            df = add2(x2[r][5], p2.y); d2 = fma2(df, df, d2);
            df = add2(x2[r][6], p3.x); d2 = fma2(df, df, d2);
            df = add2(x2[r][7], p3.y); d2 = fma2(df, df, d2);
            df = add2(x2[r][8], p4.x); d2 = fma2(df, df, d2);
            df = add2(x2[r][9], p4.y); d2 = fma2(df, df, d2);
            float da, db; upk2(d2, da, db);
            // dist = d2 * rsqrt(d2)  (d2 > 0 w.p. 1 for random inputs)
            float ea = __expf(-da * __frsqrt_rn(da));
            float eb = __expf(-db * __frsqrt_rn(db));
            e2[r] = pk2(ea, eb);
            den2[r] = add2(den2[r], e2[r]);
        }

        // ---- MLPs for the two experts of this pair ----
        float predk[2][R];
        #pragma unroll
        for (int sub = 0; sub < 2; sub++) {
            int k = 2 * kp + sub;
            ULL pred2[R];
            #pragma unroll
            for (int r = 0; r < R; r++) pred2[r] = 0ull;

            #pragma unroll
            for (int hp = 0; hp < NHP; hp++) {
                const ulonglong2* wrow = (const ulonglong2*)(w1p + (k * NHP + hp) * DI);
                ulonglong2 w0 = wrow[0], w1v = wrow[1], w2v = wrow[2], w3 = wrow[3], w4 = wrow[4];
                ulonglong2 bwv = ((const ulonglong2*)bwp)[k * NHP + hp]; // (b1pair, w2pair)
                #pragma unroll
                for (int r = 0; r < R; r++) {
                    ULL acc = bwv.x;
                    acc = fma2(x2[r][0], w0.x,  acc);
                    acc = fma2(x2[r][1], w0.y,  acc);
                    acc = fma2(x2[r][2], w1v.x, acc);
                    acc = fma2(x2[r][3], w1v.y, acc);
                    acc = fma2(x2[r][4], w2v.x, acc);
                    acc = fma2(x2[r][5], w2v.y, acc);
                    acc = fma2(x2[r][6], w3.x,  acc);
                    acc = fma2(x2[r][7], w3.y,  acc);
                    acc = fma2(x2[r][8], w4.x,  acc);
                    acc = fma2(x2[r][9], w4.y,  acc);
                    float hl, hh; upk2(acc, hl, hh);
                    hl = fmaxf(hl, 0.0f);
                    hh = fmaxf(hh, 0.0f);
                    pred2[r] = fma2(pk2(hl, hh), bwv.y, pred2[r]);
                }
            }
            float b2k = sm[F_B2 + k];
            #pragma unroll
            for (int r = 0; r < R; r++) {
                float pl, ph; upk2(pred2[r], pl, ph);
                predk[sub][r] = b2k + pl + ph;
            }
        }

        // ---- packed num accumulation: (pred_k, pred_k+1) * (e_k, e_k+1) ----
        #pragma unroll
        for (int r = 0; r < R; r++)
            num2[r] = fma2(pk2(predk[0][r], predk[1][r]), e2[r], num2[r]);
    }

    float2 o;
    {
        float nl, nh, dl, dh;
        upk2(num2[0], nl, nh); upk2(den2[0], dl, dh);
        o.x = (nl + nh) / (dl + dh);
        upk2(num2[1], nl, nh); upk2(den2[1], dl, dh);
        o.y = (nl + nh) / (dl + dh);
    }
    ((float2*)out)[gt] = o;
}

extern "C" void kernel_launch(void* const* d_in, const int* in_sizes, int n_in,
                              void* d_out, int out_size)
{
    const float* in    = (const float*)d_in[0];
    const float* W1    = (const float*)d_in[1];
    const float* b1    = (const float*)d_in[2];
    const float* W2    = (const float*)d_in[3];
    const float* b2    = (const float*)d_in[4];
    const float* proto = (const float*)d_in[5];
    float* out = (float*)d_out;

    piecewise_mlp_kernel<<<GRID, THREADS, SM_FLOATS * sizeof(float)>>>(
        in, W1, b1, W2, b2, proto, out);
}

// round 4
// speedup vs baseline: 1.8364x; 1.8364x over previous
#include <cuda_runtime.h>

typedef unsigned long long ULL;

// ---------------- packed f32x2 helpers (sm_103a FFMA2 path) ----------------
__device__ __forceinline__ ULL pk2(float lo, float hi) {
    ULL r; asm("mov.b64 %0, {%1,%2};" : "=l"(r) : "f"(lo), "f"(hi)); return r;
}
__device__ __forceinline__ void upk2(ULL v, float& lo, float& hi) {
    asm("mov.b64 {%0,%1}, %2;" : "=f"(lo), "=f"(hi) : "l"(v));
}
__device__ __forceinline__ ULL fma2(ULL a, ULL b, ULL c) {
    ULL d; asm("fma.rn.f32x2 %0, %1, %2, %3;" : "=l"(d) : "l"(a), "l"(b), "l"(c)); return d;
}
__device__ __forceinline__ ULL add2(ULL a, ULL b) {
    ULL d; asm("add.rn.f32x2 %0, %1, %2;" : "=l"(d) : "l"(a), "l"(b)); return d;
}
__device__ __forceinline__ float rsqrt_approx(float x) {
    float r; asm("rsqrt.approx.f32 %0, %1;" : "=f"(r) : "f"(x)); return r;
}

// ---------------- problem constants ----------------
constexpr int K    = 32;       // experts
constexpr int DI   = 10;       // input size
constexpr int DH   = 20;       // hidden size
constexpr int NHP  = DH / 2;   // hidden pairs = 10
constexpr int B    = 262144;
constexpr int THREADS = 128;
constexpr int R    = 4;        // batch rows per thread
constexpr int SPLIT = 4;       // expert splits across gridDim.y
constexpr int KPC  = K / SPLIT;    // experts per CTA = 8
constexpr int NKPC = KPC / 2;      // expert pairs per CTA = 4
constexpr int GRIDX = B / (R * THREADS);   // 512

// per-split partials: entry j covers rows 2j,2j+1 as (n0,d0,n1,d1)
__device__ float4 g_part[SPLIT][B / 2];

// shared layout in ULL units (per CTA: 8 experts only)
constexpr int U_W1 = 0;                       // [kl][hp][i] : 800 ULL
constexpr int U_BW = U_W1 + KPC * NHP * DI;   // [kl][hp]{(b1,b1'),(w2,w2')} : 160 ULL
constexpr int U_P  = U_BW + KPC * NHP * 2;    // [kpl][i] (-p2k,-p2k+1) : 40 ULL
constexpr int U_END = U_P + NKPC * DI;        // 1000 ULL
constexpr int F_B2 = U_END * 2;               // float idx 2000
constexpr int SM_FLOATS = F_B2 + KPC;         // 2008 floats ~ 8 KB

__global__ void __launch_bounds__(THREADS)
piecewise_mlp_main(const float* __restrict__ in,
                   const float* __restrict__ W1,
                   const float* __restrict__ b1,
                   const float* __restrict__ W2,
                   const float* __restrict__ b2,
                   const float* __restrict__ proto)
{
    extern __shared__ float sm[];
    ULL* smU = (ULL*)sm;
    const int split = blockIdx.y;
    const int kbase = split * KPC;

    // ---- stage this split's 8 experts ----
    for (int idx = threadIdx.x; idx < KPC * NHP * DI; idx += THREADS) {
        int kl = idx / (NHP * DI), rem = idx % (NHP * DI);
        int hp = rem / DI, i = rem % DI;
        int k = kbase + kl;
        smU[U_W1 + idx] = pk2(W1[(k * DH + 2 * hp) * DI + i],
                              W1[(k * DH + 2 * hp + 1) * DI + i]);
    }
    for (int idx = threadIdx.x; idx < KPC * NHP * 2; idx += THREADS) {
        int kl = idx / (NHP * 2), rem = idx % (NHP * 2);
        int hp = rem / 2, w = rem % 2;
        int k = kbase + kl;
        const float* src = (w == 0) ? b1 : W2;   // W2 is [K,1,DH] flat
        smU[U_BW + idx] = pk2(src[k * DH + 2 * hp], src[k * DH + 2 * hp + 1]);
    }
    for (int idx = threadIdx.x; idx < NKPC * DI; idx += THREADS) {
        int kpl = idx / DI, i = idx % DI;
        int k = kbase + 2 * kpl;
        smU[U_P + idx] = pk2(-proto[k * DI + i], -proto[(k + 1) * DI + i]);
    }
    for (int idx = threadIdx.x; idx < KPC; idx += THREADS)
        sm[F_B2 + idx] = b2[kbase + idx];
    __syncthreads();

    // ---- load R=4 batch rows (160B contiguous), build dup packs (x,x) ----
    const int gt = blockIdx.x * THREADS + threadIdx.x;
    const float4* q = (const float4*)(in + (size_t)gt * R * DI);
    ULL x2[R][DI];
    #pragma unroll
    for (int v = 0; v < R * DI / 4; v++) {     // 10 float4 loads
        float4 f = q[v];
        int b0 = v * 4;
        x2[(b0 + 0) / DI][(b0 + 0) % DI] = pk2(f.x, f.x);
        x2[(b0 + 1) / DI][(b0 + 1) % DI] = pk2(f.y, f.y);
        x2[(b0 + 2) / DI][(b0 + 2) % DI] = pk2(f.z, f.z);
        x2[(b0 + 3) / DI][(b0 + 3) % DI] = pk2(f.w, f.w);
    }

    ULL num2[R], den2[R];
    #pragma unroll
    for (int r = 0; r < R; r++) { num2[r] = 0ull; den2[r] = 0ull; }

    const ULL* w1p = smU + U_W1;
    const ULL* bwp = smU + U_BW;
    const ULL* ppp = smU + U_P;

    #pragma unroll 1
    for (int kp = 0; kp < NKPC; kp++) {
        // ---- gating for local expert pair (2kp, 2kp+1), all rows, packed over experts ----
        const ulonglong2* pq = (const ulonglong2*)(ppp + kp * DI);
        ulonglong2 p0 = pq[0], p1 = pq[1], p2 = pq[2], p3 = pq[3], p4 = pq[4];
        ULL e2[R];
        #pragma unroll
        for (int r = 0; r < R; r++) {
            ULL d2 = 0ull, df;
            df = add2(x2[r][0], p0.x); d2 = fma2(df, df, d2);
            df = add2(x2[r][1], p0.y); d2 = fma2(df, df, d2);
            df = add2(x2[r][2], p1.x); d2 = fma2(df, df, d2);
            df = add2(x2[r][3], p1.y); d2 = fma2(df, df, d2);
            df = add2(x2[r][4], p2.x); d2 = fma2(df, df, d2);
            df = add2(x2[r][5], p2.y); d2 = fma2(df, df, d2);
            df = add2(x2[r][6], p3.x); d2 = fma2(df, df, d2);
            df = add2(x2[r][7], p3.y); d2 = fma2(df, df, d2);
            df = add2(x2[r][8], p4.x); d2 = fma2(df, df, d2);
            df = add2(x2[r][9], p4.y); d2 = fma2(df, df, d2);
            float da, db; upk2(d2, da, db);
            // dist = d2 * rsqrt(d2)  — MUFU.RSQ, rel err 2^-22
            float ea = __expf(-da * rsqrt_approx(da));
            float eb = __expf(-db * rsqrt_approx(db));
            e2[r] = pk2(ea, eb);
            den2[r] = add2(den2[r], e2[r]);
        }

        // ---- MLPs for the two experts of this pair ----
        float predk[2][R];
        #pragma unroll
        for (int sub = 0; sub < 2; sub++) {
            int kl = 2 * kp + sub;
            ULL pred2[R];
            #pragma unroll
            for (int r = 0; r < R; r++) pred2[r] = 0ull;

            #pragma unroll
            for (int hp = 0; hp < NHP; hp++) {
                const ulonglong2* wrow = (const ulonglong2*)(w1p + (kl * NHP + hp) * DI);
                ulonglong2 w0 = wrow[0], w1v = wrow[1], w2v = wrow[2], w3 = wrow[3], w4 = wrow[4];
                ulonglong2 bwv = ((const ulonglong2*)bwp)[kl * NHP + hp]; // (b1pair, w2pair)
                #pragma unroll
                for (int r = 0; r < R; r++) {
                    ULL acc = bwv.x;
                    acc = fma2(x2[r][0], w0.x,  acc);
                    acc = fma2(x2[r][1], w0.y,  acc);
                    acc = fma2(x2[r][2], w1v.x, acc);
                    acc = fma2(x2[r][3], w1v.y, acc);
                    acc = fma2(x2[r][4], w2v.x, acc);
                    acc = fma2(x2[r][5], w2v.y, acc);
                    acc = fma2(x2[r][6], w3.x,  acc);
                    acc = fma2(x2[r][7], w3.y,  acc);
                    acc = fma2(x2[r][8], w4.x,  acc);
                    acc = fma2(x2[r][9], w4.y,  acc);
                    float hl, hh; upk2(acc, hl, hh);
                    hl = fmaxf(hl, 0.0f);
                    hh = fmaxf(hh, 0.0f);
                    pred2[r] = fma2(pk2(hl, hh), bwv.y, pred2[r]);
                }
            }
            float b2k = sm[F_B2 + kl];
            #pragma unroll
            for (int r = 0; r < R; r++) {
                float pl, ph; upk2(pred2[r], pl, ph);
                predk[sub][r] = b2k + pl + ph;
            }
        }

        // ---- packed num accumulation: (pred_k, pred_k+1) * (e_k, e_k+1) ----
        #pragma unroll
        for (int r = 0; r < R; r++)
            num2[r] = fma2(pk2(predk[0][r], predk[1][r]), e2[r], num2[r]);
    }

    // ---- write partial (num, den) per row for this split ----
    float n[R], d[R];
    #pragma unroll
    for (int r = 0; r < R; r++) {
        float nl, nh, dl, dh;
        upk2(num2[r], nl, nh); upk2(den2[r], dl, dh);
        n[r] = nl + nh;
        d[r] = dl + dh;
    }
    float4* dst = &g_part[split][(size_t)gt * 2];
    dst[0] = make_float4(n[0], d[0], n[1], d[1]);
    dst[1] = make_float4(n[2], d[2], n[3], d[3]);
}

// ---- combine: out[row] = sum_s num / sum_s den ----
constexpr int CTHREADS = 256;
constexpr int CGRID = B / (4 * CTHREADS);   // 256; each thread does 4 rows

__global__ void __launch_bounds__(CTHREADS)
piecewise_mlp_combine(float* __restrict__ out)
{
    const int t = blockIdx.x * CTHREADS + threadIdx.x;   // 4-row group index
    float n[4] = {0, 0, 0, 0}, d[4] = {0, 0, 0, 0};
    #pragma unroll
    for (int s = 0; s < SPLIT; s++) {
        float4 a = g_part[s][(size_t)t * 2];
        float4 b = g_part[s][(size_t)t * 2 + 1];
        n[0] += a.x; d[0] += a.y;
        n[1] += a.z; d[1] += a.w;
        n[2] += b.x; d[2] += b.y;
        n[3] += b.z; d[3] += b.w;
    }
    float4 o;
    o.x = n[0] / d[0];
    o.y = n[1] / d[1];
    o.z = n[2] / d[2];
    o.w = n[3] / d[3];
    ((float4*)out)[t] = o;
}

extern "C" void kernel_launch(void* const* d_in, const int* in_sizes, int n_in,
                              void* d_out, int out_size)
{
    const float* in    = (const float*)d_in[0];
    const float* W1    = (const float*)d_in[1];
    const float* b1    = (const float*)d_in[2];
    const float* W2    = (const float*)d_in[3];
    const float* b2    = (const float*)d_in[4];
    const float* proto = (const float*)d_in[5];
    float* out = (float*)d_out;

    dim3 grid(GRIDX, SPLIT);
    piecewise_mlp_main<<<grid, THREADS, SM_FLOATS * sizeof(float)>>>(
        in, W1, b1, W2, b2, proto);
    piecewise_mlp_combine<<<CGRID, CTHREADS>>>(out);
}

// round 5
// speedup vs baseline: 1.8408x; 1.0024x over previous
#include <cuda_runtime.h>

typedef unsigned long long ULL;

// ---------------- packed f32x2 helpers (sm_103a FFMA2 path) ----------------
__device__ __forceinline__ ULL pk2(float lo, float hi) {
    ULL r; asm("mov.b64 %0, {%1,%2};" : "=l"(r) : "f"(lo), "f"(hi)); return r;
}
__device__ __forceinline__ void upk2(ULL v, float& lo, float& hi) {
    asm("mov.b64 {%0,%1}, %2;" : "=f"(lo), "=f"(hi) : "l"(v));
}
__device__ __forceinline__ ULL fma2(ULL a, ULL b, ULL c) {
    ULL d; asm("fma.rn.f32x2 %0, %1, %2, %3;" : "=l"(d) : "l"(a), "l"(b), "l"(c)); return d;
}
__device__ __forceinline__ ULL add2(ULL a, ULL b) {
    ULL d; asm("add.rn.f32x2 %0, %1, %2;" : "=l"(d) : "l"(a), "l"(b)); return d;
}
__device__ __forceinline__ float rsqrt_approx(float x) {
    float r; asm("rsqrt.approx.f32 %0, %1;" : "=f"(r) : "f"(x)); return r;
}

// ---------------- problem constants ----------------
constexpr int K    = 32;       // experts
constexpr int DI   = 10;       // input size
constexpr int DH   = 20;       // hidden size
constexpr int NHP  = DH / 2;   // hidden pairs = 10
constexpr int B    = 262144;
constexpr int THREADS = 128;
constexpr int R    = 4;        // batch rows per thread
constexpr int SPLIT = 4;       // expert splits across gridDim.y
constexpr int KPC  = K / SPLIT;    // experts per CTA = 8
constexpr int NKPC = KPC / 2;      // expert pairs per CTA = 4
constexpr int GRIDX = B / (R * THREADS);   // 512

// per-split partials: entry j covers rows 2j,2j+1 as (n0,d0,n1,d1)
__device__ float4 g_part[SPLIT][B / 2];

// shared layout in ULL units (per CTA: 8 experts only)
constexpr int U_W1 = 0;                       // [kl][hp][i] : 800 ULL
constexpr int U_BW = U_W1 + KPC * NHP * DI;   // [kl][hp]{(b1,b1'),(w2,w2')} : 160 ULL
constexpr int U_P  = U_BW + KPC * NHP * 2;    // [kpl][i] (-p2k,-p2k+1) : 40 ULL
constexpr int U_END = U_P + NKPC * DI;        // 1000 ULL
constexpr int F_B2 = U_END * 2;               // float idx 2000
constexpr int SM_FLOATS = F_B2 + KPC;         // 2008 floats ~ 8 KB

__global__ void __launch_bounds__(THREADS)
piecewise_mlp_main(const float* __restrict__ in,
                   const float* __restrict__ W1,
                   const float* __restrict__ b1,
                   const float* __restrict__ W2,
                   const float* __restrict__ b2,
                   const float* __restrict__ proto)
{
    extern __shared__ float sm[];
    ULL* smU = (ULL*)sm;
    const int split = blockIdx.y;
    const int kbase = split * KPC;

    // ---- stage this split's 8 experts ----
    for (int idx = threadIdx.x; idx < KPC * NHP * DI; idx += THREADS) {
        int kl = idx / (NHP * DI), rem = idx % (NHP * DI);
        int hp = rem / DI, i = rem % DI;
        int k = kbase + kl;
        smU[U_W1 + idx] = pk2(W1[(k * DH + 2 * hp) * DI + i],
                              W1[(k * DH + 2 * hp + 1) * DI + i]);
    }
    for (int idx = threadIdx.x; idx < KPC * NHP * 2; idx += THREADS) {
        int kl = idx / (NHP * 2), rem = idx % (NHP * 2);
        int hp = rem / 2, w = rem % 2;
        int k = kbase + kl;
        const float* src = (w == 0) ? b1 : W2;   // W2 is [K,1,DH] flat
        smU[U_BW + idx] = pk2(src[k * DH + 2 * hp], src[k * DH + 2 * hp + 1]);
    }
    for (int idx = threadIdx.x; idx < NKPC * DI; idx += THREADS) {
        int kpl = idx / DI, i = idx % DI;
        int k = kbase + 2 * kpl;
        smU[U_P + idx] = pk2(-proto[k * DI + i], -proto[(k + 1) * DI + i]);
    }
    for (int idx = threadIdx.x; idx < KPC; idx += THREADS)
        sm[F_B2 + idx] = b2[kbase + idx];
    __syncthreads();

    // ---- load R=4 batch rows (160B contiguous), build dup packs (x,x) ----
    const int gt = blockIdx.x * THREADS + threadIdx.x;
    const float4* q = (const float4*)(in + (size_t)gt * R * DI);
    ULL x2[R][DI];
    #pragma unroll
    for (int v = 0; v < R * DI / 4; v++) {     // 10 float4 loads
        float4 f = q[v];
        int b0 = v * 4;
        x2[(b0 + 0) / DI][(b0 + 0) % DI] = pk2(f.x, f.x);
        x2[(b0 + 1) / DI][(b0 + 1) % DI] = pk2(f.y, f.y);
        x2[(b0 + 2) / DI][(b0 + 2) % DI] = pk2(f.z, f.z);
        x2[(b0 + 3) / DI][(b0 + 3) % DI] = pk2(f.w, f.w);
    }

    ULL num2[R], den2[R];
    #pragma unroll
    for (int r = 0; r < R; r++) { num2[r] = 0ull; den2[r] = 0ull; }

    const ULL* w1p = smU + U_W1;
    const ULL* bwp = smU + U_BW;
    const ULL* ppp = smU + U_P;

    #pragma unroll 1
    for (int kp = 0; kp < NKPC; kp++) {
        // ---- gating for local expert pair (2kp, 2kp+1), all rows, packed over experts ----
        const ulonglong2* pq = (const ulonglong2*)(ppp + kp * DI);
        ulonglong2 p0 = pq[0], p1 = pq[1], p2 = pq[2], p3 = pq[3], p4 = pq[4];
        ULL e2[R];
        #pragma unroll
        for (int r = 0; r < R; r++) {
            ULL d2 = 0ull, df;
            df = add2(x2[r][0], p0.x); d2 = fma2(df, df, d2);
            df = add2(x2[r][1], p0.y); d2 = fma2(df, df, d2);
            df = add2(x2[r][2], p1.x); d2 = fma2(df, df, d2);
            df = add2(x2[r][3], p1.y); d2 = fma2(df, df, d2);
            df = add2(x2[r][4], p2.x); d2 = fma2(df, df, d2);
            df = add2(x2[r][5], p2.y); d2 = fma2(df, df, d2);
            df = add2(x2[r][6], p3.x); d2 = fma2(df, df, d2);
            df = add2(x2[r][7], p3.y); d2 = fma2(df, df, d2);
            df = add2(x2[r][8], p4.x); d2 = fma2(df, df, d2);
            df = add2(x2[r][9], p4.y); d2 = fma2(df, df, d2);
            float da, db; upk2(d2, da, db);
            // dist = d2 * rsqrt(d2)  — MUFU.RSQ, rel err 2^-22
            float ea = __expf(-da * rsqrt_approx(da));
            float eb = __expf(-db * rsqrt_approx(db));
            e2[r] = pk2(ea, eb);
            den2[r] = add2(den2[r], e2[r]);
        }

        // ---- MLPs for the two experts of this pair ----
        float predk[2][R];
        #pragma unroll
        for (int sub = 0; sub < 2; sub++) {
            int kl = 2 * kp + sub;
            ULL pred2[R];
            #pragma unroll
            for (int r = 0; r < R; r++) pred2[r] = 0ull;

            #pragma unroll
            for (int hp = 0; hp < NHP; hp++) {
                const ulonglong2* wrow = (const ulonglong2*)(w1p + (kl * NHP + hp) * DI);
                ulonglong2 w0 = wrow[0], w1v = wrow[1], w2v = wrow[2], w3 = wrow[3], w4 = wrow[4];
                ulonglong2 bwv = ((const ulonglong2*)bwp)[kl * NHP + hp]; // (b1pair, w2pair)
                #pragma unroll
                for (int r = 0; r < R; r++) {
                    ULL acc = bwv.x;
                    acc = fma2(x2[r][0], w0.x,  acc);
                    acc = fma2(x2[r][1], w0.y,  acc);
                    acc = fma2(x2[r][2], w1v.x, acc);
                    acc = fma2(x2[r][3], w1v.y, acc);
                    acc = fma2(x2[r][4], w2v.x, acc);
                    acc = fma2(x2[r][5], w2v.y, acc);
                    acc = fma2(x2[r][6], w3.x,  acc);
                    acc = fma2(x2[r][7], w3.y,  acc);
                    acc = fma2(x2[r][8], w4.x,  acc);
                    acc = fma2(x2[r][9], w4.y,  acc);
                    float hl, hh; upk2(acc, hl, hh);
                    hl = fmaxf(hl, 0.0f);
                    hh = fmaxf(hh, 0.0f);
                    pred2[r] = fma2(pk2(hl, hh), bwv.y, pred2[r]);
                }
            }
            float b2k = sm[F_B2 + kl];
            #pragma unroll
            for (int r = 0; r < R; r++) {
                float pl, ph; upk2(pred2[r], pl, ph);
                predk[sub][r] = b2k + pl + ph;
            }
        }

        // ---- packed num accumulation: (pred_k, pred_k+1) * (e_k, e_k+1) ----
        #pragma unroll
        for (int r = 0; r < R; r++)
            num2[r] = fma2(pk2(predk[0][r], predk[1][r]), e2[r], num2[r]);
    }

    // ---- write partial (num, den) per row for this split ----
    float n[R], d[R];
    #pragma unroll
    for (int r = 0; r < R; r++) {
        float nl, nh, dl, dh;
        upk2(num2[r], nl, nh); upk2(den2[r], dl, dh);
        n[r] = nl + nh;
        d[r] = dl + dh;
    }
    float4* dst = &g_part[split][(size_t)gt * 2];
    dst[0] = make_float4(n[0], d[0], n[1], d[1]);
    dst[1] = make_float4(n[2], d[2], n[3], d[3]);
}

// ---- combine: out[row] = sum_s num / sum_s den ----
constexpr int CTHREADS = 256;
constexpr int CGRID = B / (4 * CTHREADS);   // 256; each thread does 4 rows

__global__ void __launch_bounds__(CTHREADS)
piecewise_mlp_combine(float* __restrict__ out)
{
    const int t = blockIdx.x * CTHREADS + threadIdx.x;   // 4-row group index
    float n[4] = {0, 0, 0, 0}, d[4] = {0, 0, 0, 0};
    #pragma unroll
    for (int s = 0; s < SPLIT; s++) {
        float4 a = g_part[s][(size_t)t * 2];
        float4 b = g_part[s][(size_t)t * 2 + 1];
        n[0] += a.x; d[0] += a.y;
        n[1] += a.z; d[1] += a.w;
        n[2] += b.x; d[2] += b.y;
        n[3] += b.z; d[3] += b.w;
    }
    float4 o;
    o.x = n[0] / d[0];
    o.y = n[1] / d[1];
    o.z = n[2] / d[2];
    o.w = n[3] / d[3];
    ((float4*)out)[t] = o;
}

extern "C" void kernel_launch(void* const* d_in, const int* in_sizes, int n_in,
                              void* d_out, int out_size)
{
    const float* in    = (const float*)d_in[0];
    const float* W1    = (const float*)d_in[1];
    const float* b1    = (const float*)d_in[2];
    const float* W2    = (const float*)d_in[3];
    const float* b2    = (const float*)d_in[4];
    const float* proto = (const float*)d_in[5];
    float* out = (float*)d_out;

    dim3 grid(GRIDX, SPLIT);
    piecewise_mlp_main<<<grid, THREADS, SM_FLOATS * sizeof(float)>>>(
        in, W1, b1, W2, b2, proto);
    piecewise_mlp_combine<<<CGRID, CTHREADS>>>(out);
}

// round 6
// speedup vs baseline: 1.8481x; 1.0040x over previous
#include <cuda_runtime.h>

typedef unsigned long long ULL;

// ---------------- packed f32x2 helpers (sm_103a FFMA2 path) ----------------
__device__ __forceinline__ ULL pk2(float lo, float hi) {
    ULL r; asm("mov.b64 %0, {%1,%2};" : "=l"(r) : "f"(lo), "f"(hi)); return r;
}
__device__ __forceinline__ void upk2(ULL v, float& lo, float& hi) {
    asm("mov.b64 {%0,%1}, %2;" : "=f"(lo), "=f"(hi) : "l"(v));
}
__device__ __forceinline__ ULL fma2(ULL a, ULL b, ULL c) {
    ULL d; asm("fma.rn.f32x2 %0, %1, %2, %3;" : "=l"(d) : "l"(a), "l"(b), "l"(c)); return d;
}
__device__ __forceinline__ ULL add2(ULL a, ULL b) {
    ULL d; asm("add.rn.f32x2 %0, %1, %2;" : "=l"(d) : "l"(a), "l"(b)); return d;
}
__device__ __forceinline__ float rsqrt_approx(float x) {
    float r; asm("rsqrt.approx.f32 %0, %1;" : "=f"(r) : "f"(x)); return r;
}

// ---------------- problem constants ----------------
constexpr int K    = 32;       // experts
constexpr int DI   = 10;       // input size
constexpr int DH   = 20;       // hidden size
constexpr int NHP  = DH / 2;   // hidden pairs = 10
constexpr int B    = 262144;
constexpr int THREADS = 128;
constexpr int R    = 4;        // batch rows per thread
constexpr int SPLIT = 4;       // expert splits across gridDim.y
constexpr int KPC  = K / SPLIT;    // experts per CTA = 8
constexpr int NKPC = KPC / 2;      // expert pairs per CTA = 4
constexpr int GRIDX = B / (R * THREADS);   // 512

// per-split partials: entry j covers rows 2j,2j+1 as (n0,d0,n1,d1)
__device__ float4 g_part[SPLIT][B / 2];

// shared layout in ULL units (per CTA: 8 experts only)
constexpr int U_W1 = 0;                       // [kl][hp][i] : 800 ULL
constexpr int U_BW = U_W1 + KPC * NHP * DI;   // [kl][hp]{(b1,b1'),(w2,w2')} : 160 ULL
constexpr int U_P  = U_BW + KPC * NHP * 2;    // [kpl][i] (-p2k,-p2k+1) : 40 ULL
constexpr int U_END = U_P + NKPC * DI;        // 1000 ULL
constexpr int F_B2 = U_END * 2;               // float idx 2000
constexpr int SM_FLOATS = F_B2 + KPC;         // 2008 floats ~ 8 KB

__global__ void __launch_bounds__(THREADS)
piecewise_mlp_main(const float* __restrict__ in,
                   const float* __restrict__ W1,
                   const float* __restrict__ b1,
                   const float* __restrict__ W2,
                   const float* __restrict__ b2,
                   const float* __restrict__ proto)
{
    extern __shared__ float sm[];
    ULL* smU = (ULL*)sm;
    const int split = blockIdx.y;
    const int kbase = split * KPC;

    // ---- stage this split's 8 experts ----
    for (int idx = threadIdx.x; idx < KPC * NHP * DI; idx += THREADS) {
        int kl = idx / (NHP * DI), rem = idx % (NHP * DI);
        int hp = rem / DI, i = rem % DI;
        int k = kbase + kl;
        smU[U_W1 + idx] = pk2(W1[(k * DH + 2 * hp) * DI + i],
                              W1[(k * DH + 2 * hp + 1) * DI + i]);
    }
    for (int idx = threadIdx.x; idx < KPC * NHP * 2; idx += THREADS) {
        int kl = idx / (NHP * 2), rem = idx % (NHP * 2);
        int hp = rem / 2, w = rem % 2;
        int k = kbase + kl;
        const float* src = (w == 0) ? b1 : W2;   // W2 is [K,1,DH] flat
        smU[U_BW + idx] = pk2(src[k * DH + 2 * hp], src[k * DH + 2 * hp + 1]);
    }
    for (int idx = threadIdx.x; idx < NKPC * DI; idx += THREADS) {
        int kpl = idx / DI, i = idx % DI;
        int k = kbase + 2 * kpl;
        smU[U_P + idx] = pk2(-proto[k * DI + i], -proto[(k + 1) * DI + i]);
    }
    for (int idx = threadIdx.x; idx < KPC; idx += THREADS)
        sm[F_B2 + idx] = b2[kbase + idx];
    __syncthreads();

    // ---- load R=4 batch rows (160B contiguous), build dup packs (x,x) ----
    const int gt = blockIdx.x * THREADS + threadIdx.x;
    const float4* q = (const float4*)(in + (size_t)gt * R * DI);
    ULL x2[R][DI];
    #pragma unroll
    for (int v = 0; v < R * DI / 4; v++) {     // 10 float4 loads
        float4 f = q[v];
        int b0 = v * 4;
        x2[(b0 + 0) / DI][(b0 + 0) % DI] = pk2(f.x, f.x);
        x2[(b0 + 1) / DI][(b0 + 1) % DI] = pk2(f.y, f.y);
        x2[(b0 + 2) / DI][(b0 + 2) % DI] = pk2(f.z, f.z);
        x2[(b0 + 3) / DI][(b0 + 3) % DI] = pk2(f.w, f.w);
    }

    ULL num2[R], den2[R];
    #pragma unroll
    for (int r = 0; r < R; r++) { num2[r] = 0ull; den2[r] = 0ull; }

    const ULL* w1p = smU + U_W1;
    const ULL* bwp = smU + U_BW;
    const ULL* ppp = smU + U_P;

    #pragma unroll 1
    for (int kp = 0; kp < NKPC; kp++) {
        // ---- gating for local expert pair (2kp, 2kp+1), all rows, packed over experts ----
        const ulonglong2* pq = (const ulonglong2*)(ppp + kp * DI);
        ulonglong2 p0 = pq[0], p1 = pq[1], p2 = pq[2], p3 = pq[3], p4 = pq[4];
        ULL e2[R];
        #pragma unroll
        for (int r = 0; r < R; r++) {
            ULL d2 = 0ull, df;
            df = add2(x2[r][0], p0.x); d2 = fma2(df, df, d2);
            df = add2(x2[r][1], p0.y); d2 = fma2(df, df, d2);
            df = add2(x2[r][2], p1.x); d2 = fma2(df, df, d2);
            df = add2(x2[r][3], p1.y); d2 = fma2(df, df, d2);
            df = add2(x2[r][4], p2.x); d2 = fma2(df, df, d2);
            df = add2(x2[r][5], p2.y); d2 = fma2(df, df, d2);
            df = add2(x2[r][6], p3.x); d2 = fma2(df, df, d2);
            df = add2(x2[r][7], p3.y); d2 = fma2(df, df, d2);
            df = add2(x2[r][8], p4.x); d2 = fma2(df, df, d2);
            df = add2(x2[r][9], p4.y); d2 = fma2(df, df, d2);
            float da, db; upk2(d2, da, db);
            // dist = d2 * rsqrt(d2)  — MUFU.RSQ, rel err 2^-22
            float ea = __expf(-da * rsqrt_approx(da));
            float eb = __expf(-db * rsqrt_approx(db));
            e2[r] = pk2(ea, eb);
            den2[r] = add2(den2[r], e2[r]);
        }

        // ---- MLPs for the two experts of this pair ----
        float predk[2][R];
        #pragma unroll
        for (int sub = 0; sub < 2; sub++) {
            int kl = 2 * kp + sub;
            ULL pred2[R];
            #pragma unroll
            for (int r = 0; r < R; r++) pred2[r] = 0ull;

            #pragma unroll
            for (int hp = 0; hp < NHP; hp++) {
                const ulonglong2* wrow = (const ulonglong2*)(w1p + (kl * NHP + hp) * DI);
                ulonglong2 w0 = wrow[0], w1v = wrow[1], w2v = wrow[2], w3 = wrow[3], w4 = wrow[4];
                ulonglong2 bwv = ((const ulonglong2*)bwp)[kl * NHP + hp]; // (b1pair, w2pair)
                #pragma unroll
                for (int r = 0; r < R; r++) {
                    ULL acc = bwv.x;
                    acc = fma2(x2[r][0], w0.x,  acc);
                    acc = fma2(x2[r][1], w0.y,  acc);
                    acc = fma2(x2[r][2], w1v.x, acc);
                    acc = fma2(x2[r][3], w1v.y, acc);
                    acc = fma2(x2[r][4], w2v.x, acc);
                    acc = fma2(x2[r][5], w2v.y, acc);
                    acc = fma2(x2[r][6], w3.x,  acc);
                    acc = fma2(x2[r][7], w3.y,  acc);
                    acc = fma2(x2[r][8], w4.x,  acc);
                    acc = fma2(x2[r][9], w4.y,  acc);
                    float hl, hh; upk2(acc, hl, hh);
                    hl = fmaxf(hl, 0.0f);
                    hh = fmaxf(hh, 0.0f);
                    pred2[r] = fma2(pk2(hl, hh), bwv.y, pred2[r]);
                }
            }
            float b2k = sm[F_B2 + kl];
            #pragma unroll
            for (int r = 0; r < R; r++) {
                float pl, ph; upk2(pred2[r], pl, ph);
                predk[sub][r] = b2k + pl + ph;
            }
        }

        // ---- packed num accumulation: (pred_k, pred_k+1) * (e_k, e_k+1) ----
        #pragma unroll
        for (int r = 0; r < R; r++)
            num2[r] = fma2(pk2(predk[0][r], predk[1][r]), e2[r], num2[r]);
    }

    // ---- write partial (num, den) per row for this split ----
    float n[R], d[R];
    #pragma unroll
    for (int r = 0; r < R; r++) {
        float nl, nh, dl, dh;
        upk2(num2[r], nl, nh); upk2(den2[r], dl, dh);
        n[r] = nl + nh;
        d[r] = dl + dh;
    }
    float4* dst = &g_part[split][(size_t)gt * 2];
    dst[0] = make_float4(n[0], d[0], n[1], d[1]);
    dst[1] = make_float4(n[2], d[2], n[3], d[3]);
}

// ---- combine: out[row] = sum_s num / sum_s den ----
constexpr int CTHREADS = 256;
constexpr int CGRID = B / (4 * CTHREADS);   // 256; each thread does 4 rows

__global__ void __launch_bounds__(CTHREADS)
piecewise_mlp_combine(float* __restrict__ out)
{
    const int t = blockIdx.x * CTHREADS + threadIdx.x;   // 4-row group index
    float n[4] = {0, 0, 0, 0}, d[4] = {0, 0, 0, 0};
    #pragma unroll
    for (int s = 0; s < SPLIT; s++) {
        float4 a = g_part[s][(size_t)t * 2];
        float4 b = g_part[s][(size_t)t * 2 + 1];
        n[0] += a.x; d[0] += a.y;
        n[1] += a.z; d[1] += a.w;
        n[2] += b.x; d[2] += b.y;
        n[3] += b.z; d[3] += b.w;
    }
    float4 o;
    o.x = n[0] / d[0];
    o.y = n[1] / d[1];
    o.z = n[2] / d[2];
    o.w = n[3] / d[3];
    ((float4*)out)[t] = o;
}

extern "C" void kernel_launch(void* const* d_in, const int* in_sizes, int n_in,
                              void* d_out, int out_size)
{
    const float* in    = (const float*)d_in[0];
    const float* W1    = (const float*)d_in[1];
    const float* b1    = (const float*)d_in[2];
    const float* W2    = (const float*)d_in[3];
    const float* b2    = (const float*)d_in[4];
    const float* proto = (const float*)d_in[5];
    float* out = (float*)d_out;

    dim3 grid(GRIDX, SPLIT);
    piecewise_mlp_main<<<grid, THREADS, SM_FLOATS * sizeof(float)>>>(
        in, W1, b1, W2, b2, proto);
    piecewise_mlp_combine<<<CGRID, CTHREADS>>>(out);
}